// round 6
// baseline (speedup 1.0000x reference)
#include <cuda_runtime.h>
#include <cstdint>

// Problem constants
#define B 128
#define T 512
#define I 50
#define H 256

// recurrence config: 256 threads, thread = neuron n. 2 batch rows per CTA.
// W[n, 0:64] from SMEM (pitch 68, conflict-free), W[n, 64:256] in registers (96 ull).
// h is read as pure same-address broadcast LDS.128 (1 wavefront each).
#define K_SM   64
#define K_RG   192
#define WPITCH 68

// Scratch: xp[dir][t][b][h]  (fp32), 134 MB
__device__ float g_xp[2u * T * B * H];

// ---------------------------------------------------------------------------
// packed fp32x2 helpers (Blackwell)
// ---------------------------------------------------------------------------
__device__ __forceinline__ unsigned long long ffma2(unsigned long long a,
                                                    unsigned long long b,
                                                    unsigned long long c) {
    unsigned long long d;
    asm("fma.rn.f32x2 %0, %1, %2, %3;" : "=l"(d) : "l"(a), "l"(b), "l"(c));
    return d;
}
__device__ __forceinline__ float2 u2f(unsigned long long v) {
    float2 f;
    asm("mov.b64 {%0, %1}, %2;" : "=f"(f.x), "=f"(f.y) : "l"(v));
    return f;
}
__device__ __forceinline__ unsigned long long f2u(float lo, float hi) {
    unsigned long long v;
    asm("mov.b64 %0, {%1, %2};" : "=l"(v) : "f"(lo), "f"(hi));
    return v;
}

// ---------------------------------------------------------------------------
// Kernel 1: input projection (unchanged — not the bottleneck)
// ---------------------------------------------------------------------------
#define IPAD 52
__global__ __launch_bounds__(256) void proj_kernel(
    const float* __restrict__ x,
    const float* __restrict__ w_ih_f, const float* __restrict__ b_ih_f, const float* __restrict__ b_hh_f,
    const float* __restrict__ w_ih_b, const float* __restrict__ b_ih_b, const float* __restrict__ b_hh_b)
{
    __shared__ float xs[B * IPAD];

    const int t   = blockIdx.x;
    const int dir = blockIdx.y;
    const int h   = threadIdx.x;
    const int t_src = dir ? (T - 1 - t) : t;

    for (int idx = threadIdx.x; idx < B * IPAD; idx += blockDim.x) xs[idx] = 0.f;
    __syncthreads();
    for (int idx = threadIdx.x; idx < B * I; idx += blockDim.x) {
        int b = idx / I;
        int i = idx - b * I;
        xs[b * IPAD + i] = x[((size_t)b * T + t_src) * I + i];
    }

    const float* w = dir ? w_ih_b : w_ih_f;
    unsigned long long wr[26];
    {
        const float* wp = w + (size_t)h * I;
        #pragma unroll
        for (int i = 0; i < 25; i++) wr[i] = f2u(wp[2 * i], wp[2 * i + 1]);
        wr[25] = 0ull;
    }
    const float bias = dir ? (b_ih_b[h] + b_hh_b[h]) : (b_ih_f[h] + b_hh_f[h]);

    __syncthreads();

    float* xp_out = g_xp + (((size_t)dir * T + t) * B) * H + h;
    #pragma unroll 2
    for (int b = 0; b < B; b++) {
        const ulonglong2* xb = reinterpret_cast<const ulonglong2*>(&xs[b * IPAD]);
        unsigned long long a0 = 0ull, a1 = 0ull;
        #pragma unroll
        for (int i = 0; i < 13; i++) {
            ulonglong2 xv = xb[i];
            a0 = ffma2(xv.x, wr[2 * i], a0);
            a1 = ffma2(xv.y, wr[2 * i + 1], a1);
        }
        float2 f0 = u2f(a0), f1 = u2f(a1);
        xp_out[(size_t)b * H] = bias + ((f0.x + f0.y) + (f1.x + f1.y));
    }
}

// ---------------------------------------------------------------------------
// Kernel 2: recurrence. 128 CTAs x 256 threads, 2 batch rows per CTA.
// Thread = neuron n. k in [0,64) W from SMEM, k in [64,256) W in 192 registers.
// h double-buffered in SMEM, pure-broadcast reads, one barrier per step.
// ---------------------------------------------------------------------------
__global__ __launch_bounds__(256, 1) void rnn_kernel(
    const float* __restrict__ w_hh_f,
    const float* __restrict__ w_hh_b,
    float* __restrict__ out)
{
    extern __shared__ float sm[];
    float* Wsh = sm;                     // [256][WPITCH] = 17408 floats (69,632 B)
    float* hs  = sm + 256 * WPITCH;      // [2 buf][2 rows][256] = 1024 floats

    const int dir = blockIdx.x >> 6;
    const int jb  = blockIdx.x & 63;
    const int b0  = 2 * jb;
    const int n   = threadIdx.x;

    const float* __restrict__ W = dir ? w_hh_b : w_hh_f;

    // stage W[:, 0:K_SM] into smem (pitch 68)
    for (int idx = n; idx < 256 * K_SM; idx += 256) {
        int r = idx >> 6;          // / K_SM
        int k = idx & 63;
        Wsh[r * WPITCH + k] = W[r * H + k];
    }
    // W[n, K_SM:256] -> 96 packed pairs (192 regs)
    unsigned long long wreg[96];
    {
        const ulonglong2* p = reinterpret_cast<const ulonglong2*>(W + (size_t)n * H + K_SM);
        #pragma unroll
        for (int r = 0; r < 48; r++) {
            ulonglong2 v = p[r];
            wreg[2 * r]     = v.x;
            wreg[2 * r + 1] = v.y;
        }
    }
    // zero h buffers
    for (int i = n; i < 1024; i += 256) hs[i] = 0.f;
    __syncthreads();

    const float* xp0 = g_xp + ((size_t)dir * T * B + b0) * H + n;
    const float* xp1 = xp0 + H;
    const size_t step_stride = (size_t)B * H;
    float xa = __ldg(xp0);
    float xb = __ldg(xp1);
    float* out_t = out + (size_t)dir * H + n;

    const ulonglong2* wv = reinterpret_cast<const ulonglong2*>(Wsh + n * WPITCH);

    int buf = 0;
    for (int s = 0; s < T; s++) {
        float nxa = 0.f, nxb = 0.f;
        if (s < T - 1) {
            nxa = __ldg(xp0 + (size_t)(s + 1) * step_stride);
            nxb = __ldg(xp1 + (size_t)(s + 1) * step_stride);
        }

        const ulonglong2* hA = reinterpret_cast<const ulonglong2*>(hs + buf * 512);
        const ulonglong2* hB = reinterpret_cast<const ulonglong2*>(hs + buf * 512 + 256);

        // 4 independent packed chains (2 per batch row)
        unsigned long long aA0 = 0ull, aA1 = 0ull, aB0 = 0ull, aB1 = 0ull;

        // k in [0, 64): W from shared (16 LDS.128), h broadcast
        #pragma unroll
        for (int i = 0; i < K_SM / 4; i++) {
            ulonglong2 w  = wv[i];
            ulonglong2 ha = hA[i];
            ulonglong2 hb = hB[i];
            aA0 = ffma2(w.x, ha.x, aA0);
            aA1 = ffma2(w.y, ha.y, aA1);
            aB0 = ffma2(w.x, hb.x, aB0);
            aB1 = ffma2(w.y, hb.y, aB1);
        }
        // k in [64, 256): W from regs, h broadcast
        #pragma unroll
        for (int r = 0; r < 48; r++) {
            ulonglong2 ha = hA[K_SM / 4 + r];
            ulonglong2 hb = hB[K_SM / 4 + r];
            aA0 = ffma2(wreg[2 * r],     ha.x, aA0);
            aA1 = ffma2(wreg[2 * r + 1], ha.y, aA1);
            aB0 = ffma2(wreg[2 * r],     hb.x, aB0);
            aB1 = ffma2(wreg[2 * r + 1], hb.y, aB1);
        }

        float2 fA0 = u2f(aA0), fA1 = u2f(aA1);
        float2 fB0 = u2f(aB0), fB1 = u2f(aB1);
        float h0 = fmaxf(xa + ((fA0.x + fA0.y) + (fA1.x + fA1.y)), 0.f);
        float h1 = fmaxf(xb + ((fB0.x + fB0.y) + (fB1.x + fB1.y)), 0.f);

        const int time = dir ? (T - 1 - s) : s;
        out_t[((size_t)b0 * T + time) * (2 * H)] = h0;
        out_t[((size_t)(b0 + 1) * T + time) * (2 * H)] = h1;

        const int nb = buf ^ 1;
        hs[nb * 512 + n]       = h0;
        hs[nb * 512 + 256 + n] = h1;
        __syncthreads();

        buf = nb;
        xa = nxa;
        xb = nxb;
    }
}

// ---------------------------------------------------------------------------
extern "C" void kernel_launch(void* const* d_in, const int* in_sizes, int n_in,
                              void* d_out, int out_size)
{
    const float* x      = (const float*)d_in[0];
    const float* w_ih_f = (const float*)d_in[1];
    const float* w_hh_f = (const float*)d_in[2];
    const float* b_ih_f = (const float*)d_in[3];
    const float* b_hh_f = (const float*)d_in[4];
    const float* w_ih_b = (const float*)d_in[5];
    const float* w_hh_b = (const float*)d_in[6];
    const float* b_ih_b = (const float*)d_in[7];
    const float* b_hh_b = (const float*)d_in[8];
    float* out = (float*)d_out;

    const int smem_bytes = (256 * WPITCH + 1024) * 4;   // 69632 + 4096 = 73,728 B
    static bool attr_set = false;
    if (!attr_set) {
        cudaFuncSetAttribute(rnn_kernel, cudaFuncAttributeMaxDynamicSharedMemorySize, smem_bytes);
        attr_set = true;
    }

    proj_kernel<<<dim3(T, 2), 256>>>(x, w_ih_f, b_ih_f, b_hh_f, w_ih_b, b_ih_b, b_hh_b);
    rnn_kernel<<<128, 256, smem_bytes>>>(w_hh_f, w_hh_b, out);
}

// round 7
// speedup vs baseline: 1.2456x; 1.2456x over previous
#include <cuda_runtime.h>
#include <cstdint>

// Problem constants
#define B 128
#define T 512
#define I 50
#define H 256
#define K_SMEM 96           // k-range of W in shared memory (R2 optimum — do not raise regs past ~242)
#define K_REG  160          // k-range of W in registers (80 ull = 160 regs)
#define PITCH 100           // smem pitch: quad = 25t mod 8 -> all quads covered, conflict-free LDS.128

// Scratch: xp[dir][t][b][h], padded to T+1 steps for unconditional prefetch.
__device__ float g_xp[2u * (T + 1) * B * H];

// ---------------------------------------------------------------------------
// packed fp32x2 helpers (Blackwell)
// ---------------------------------------------------------------------------
__device__ __forceinline__ unsigned long long ffma2(unsigned long long a,
                                                    unsigned long long b,
                                                    unsigned long long c) {
    unsigned long long d;
    asm("fma.rn.f32x2 %0, %1, %2, %3;" : "=l"(d) : "l"(a), "l"(b), "l"(c));
    return d;
}
__device__ __forceinline__ unsigned long long fadd2(unsigned long long a,
                                                    unsigned long long b) {
    unsigned long long d;
    asm("add.rn.f32x2 %0, %1, %2;" : "=l"(d) : "l"(a), "l"(b));
    return d;
}
__device__ __forceinline__ float2 u2f(unsigned long long v) {
    float2 f;
    asm("mov.b64 {%0, %1}, %2;" : "=f"(f.x), "=f"(f.y) : "l"(v));
    return f;
}
__device__ __forceinline__ unsigned long long f2u(float lo, float hi) {
    unsigned long long v;
    asm("mov.b64 %0, {%1, %2};" : "=l"(v) : "f"(lo), "f"(hi));
    return v;
}

// ---------------------------------------------------------------------------
// Kernel 1: fused-direction input projection.
// Block t stages x[:, t, :] ONCE; threads [0,256) compute fwd xp[0][t][:, h],
// threads [256,512) compute bwd xp[1][T-1-t][:, h] (both consume x[:, t, :]).
// ---------------------------------------------------------------------------
#define IPAD 52
__global__ __launch_bounds__(512) void proj_kernel(
    const float* __restrict__ x,
    const float* __restrict__ w_ih_f, const float* __restrict__ b_ih_f, const float* __restrict__ b_hh_f,
    const float* __restrict__ w_ih_b, const float* __restrict__ b_ih_b, const float* __restrict__ b_hh_b)
{
    __shared__ float xs[B * IPAD];   // 26.6 KB, padded rows

    const int t   = blockIdx.x;
    const int tid = threadIdx.x;
    const int h   = tid & 255;
    const int dir = tid >> 8;

    // zero padding lanes then stage x[:, t, :]
    for (int idx = tid; idx < B * IPAD; idx += blockDim.x) xs[idx] = 0.f;
    __syncthreads();
    for (int idx = tid; idx < B * I; idx += blockDim.x) {
        int b = idx / I;
        int i = idx - b * I;
        xs[b * IPAD + i] = x[((size_t)b * T + t) * I + i];
    }

    const float* w = dir ? w_ih_b : w_ih_f;
    unsigned long long wr[26];
    {
        const float* wp = w + (size_t)h * I;
        #pragma unroll
        for (int i = 0; i < 25; i++) wr[i] = f2u(wp[2 * i], wp[2 * i + 1]);
        wr[25] = 0ull;
    }
    const float bias = dir ? (b_ih_b[h] + b_hh_b[h]) : (b_ih_f[h] + b_hh_f[h]);

    __syncthreads();

    // fwd writes timestep t; bwd writes timestep T-1-t (both use x[:, t, :])
    const int tw = dir ? (T - 1 - t) : t;
    float* xp_out = g_xp + (((size_t)dir * (T + 1) + tw) * B) * H + h;
    #pragma unroll 2
    for (int b = 0; b < B; b++) {
        const ulonglong2* xb = reinterpret_cast<const ulonglong2*>(&xs[b * IPAD]);
        unsigned long long a0 = 0ull, a1 = 0ull;
        #pragma unroll
        for (int i = 0; i < 13; i++) {
            ulonglong2 xv = xb[i];
            a0 = ffma2(xv.x, wr[2 * i], a0);
            a1 = ffma2(xv.y, wr[2 * i + 1], a1);
        }
        unsigned long long asum = fadd2(a0, a1);
        float2 f = u2f(asum);
        xp_out[(size_t)b * H] = bias + (f.x + f.y);
    }
}

// ---------------------------------------------------------------------------
// Kernel 2: recurrence (R2 structure — measured best). 128 CTAs x 256 threads,
// 2 batch rows per CTA. Thread = neuron n. W[n,0:96] from SMEM (pitch 100),
// W[n,96:256] in 160 registers. h double-buffered in SMEM (broadcast reads),
// one barrier per step, unconditional xp prefetch (g_xp padded).
// ---------------------------------------------------------------------------
__global__ __launch_bounds__(256, 1) void rnn_kernel(
    const float* __restrict__ w_hh_f,
    const float* __restrict__ w_hh_b,
    float* __restrict__ out)
{
    extern __shared__ float sm[];
    float* Wsh = sm;                       // [256][PITCH]  (102,400 B)
    float* hs  = sm + 256 * PITCH;         // [2 buf][2 rows][256]

    const int dir = blockIdx.x >> 6;
    const int j   = blockIdx.x & 63;
    const int b0  = 2 * j;
    const int t   = threadIdx.x;

    const float* __restrict__ W = dir ? w_hh_b : w_hh_f;

    // W[:, 0:K_SMEM] -> smem
    for (int idx = t; idx < 256 * K_SMEM; idx += 256) {
        int n = idx / K_SMEM;
        int k = idx - n * K_SMEM;
        Wsh[n * PITCH + k] = W[n * H + k];
    }
    // W[t, K_SMEM:256] -> regs, packed (k,k+1) pairs
    ulonglong2 wreg[K_REG / 4];            // 40 x 16B = 160 floats
    {
        const ulonglong2* wrow = reinterpret_cast<const ulonglong2*>(W + (size_t)t * H + K_SMEM);
        #pragma unroll
        for (int r = 0; r < K_REG / 4; r++) wreg[r] = wrow[r];
    }
    hs[0 * 512 + 0 * 256 + t] = 0.f;
    hs[0 * 512 + 1 * 256 + t] = 0.f;
    __syncthreads();

    const float* xp0 = g_xp + ((size_t)dir * (T + 1) * B + b0) * H + t;
    const float* xp1 = xp0 + H;
    const size_t step_stride = (size_t)B * H;

    float xa = __ldg(xp0);
    float xb = __ldg(xp1);

    float* out_t = out + (size_t)dir * H + t;

    int buf = 0;
    for (int s = 0; s < T; s++) {
        // unconditional prefetch (s+1 <= T is always in-bounds thanks to padding)
        float nxa = __ldg(xp0 + (size_t)(s + 1) * step_stride);
        float nxb = __ldg(xp1 + (size_t)(s + 1) * step_stride);

        const ulonglong2* h0v = reinterpret_cast<const ulonglong2*>(hs + buf * 512);
        const ulonglong2* h1v = reinterpret_cast<const ulonglong2*>(hs + buf * 512 + 256);
        const ulonglong2* wv  = reinterpret_cast<const ulonglong2*>(Wsh + t * PITCH);

        // 4 independent packed accumulator chains (2 per batch row)
        unsigned long long aA0 = 0ull, aB0 = 0ull, aA1 = 0ull, aB1 = 0ull;

        // k in [0, K_SMEM): W from shared
        #pragma unroll
        for (int i = 0; i < K_SMEM / 4; i++) {
            ulonglong2 w  = wv[i];
            ulonglong2 ha = h0v[i];
            ulonglong2 hb = h1v[i];
            aA0 = ffma2(w.x, ha.x, aA0);
            aB0 = ffma2(w.y, ha.y, aB0);
            aA1 = ffma2(w.x, hb.x, aA1);
            aB1 = ffma2(w.y, hb.y, aB1);
        }
        // k in [K_SMEM, 256): W from regs
        #pragma unroll
        for (int r = 0; r < K_REG / 4; r++) {
            ulonglong2 w  = wreg[r];
            ulonglong2 ha = h0v[K_SMEM / 4 + r];
            ulonglong2 hb = h1v[K_SMEM / 4 + r];
            aA0 = ffma2(w.x, ha.x, aA0);
            aB0 = ffma2(w.y, ha.y, aB0);
            aA1 = ffma2(w.x, hb.x, aA1);
            aB1 = ffma2(w.y, hb.y, aB1);
        }

        // packed tail reduction
        unsigned long long sA = fadd2(aA0, aB0);
        unsigned long long sB = fadd2(aA1, aB1);
        float2 fA = u2f(sA), fB = u2f(sB);
        float h0 = fmaxf(xa + (fA.x + fA.y), 0.f);
        float h1 = fmaxf(xb + (fB.x + fB.y), 0.f);

        const int time = dir ? (T - 1 - s) : s;
        out_t[((size_t)b0 * T + time) * (2 * H)] = h0;
        out_t[((size_t)(b0 + 1) * T + time) * (2 * H)] = h1;

        const int nb = buf ^ 1;
        hs[nb * 512 + t]       = h0;
        hs[nb * 512 + 256 + t] = h1;
        __syncthreads();

        buf = nb;
        xa = nxa;
        xb = nxb;
    }
}

// ---------------------------------------------------------------------------
extern "C" void kernel_launch(void* const* d_in, const int* in_sizes, int n_in,
                              void* d_out, int out_size)
{
    const float* x      = (const float*)d_in[0];
    const float* w_ih_f = (const float*)d_in[1];
    const float* w_hh_f = (const float*)d_in[2];
    const float* b_ih_f = (const float*)d_in[3];
    const float* b_hh_f = (const float*)d_in[4];
    const float* w_ih_b = (const float*)d_in[5];
    const float* w_hh_b = (const float*)d_in[6];
    const float* b_ih_b = (const float*)d_in[7];
    const float* b_hh_b = (const float*)d_in[8];
    float* out = (float*)d_out;

    static bool attr_set = false;
    const int smem_bytes = 256 * PITCH * 4 + 2 * 2 * 256 * 4;  // 102400 + 4096 = 106496
    if (!attr_set) {
        cudaFuncSetAttribute(rnn_kernel, cudaFuncAttributeMaxDynamicSharedMemorySize, smem_bytes);
        attr_set = true;
    }

    proj_kernel<<<T, 512>>>(x, w_ih_f, b_ih_f, b_hh_f, w_ih_b, b_ih_b, b_hh_b);
    rnn_kernel<<<128, 256, smem_bytes>>>(w_hh_f, w_hh_b, out);
}

// round 8
// speedup vs baseline: 1.4952x; 1.2004x over previous
#include <cuda_runtime.h>
#include <cstdint>

// Problem constants
#define B 128
#define T 512
#define I 50
#define H 256
#define K_SMEM 96           // k-range of W kept in shared memory
#define K_REG  160          // k-range of W kept in registers
#define PITCH 100           // smem pitch in floats (conflict-free LDS.128)

// Scratch: xp[dir][t][b][h]  (fp32), 2*512*128*256 floats = 134 MB
__device__ float g_xp[2u * T * B * H];

// ---------------------------------------------------------------------------
// packed fp32x2 helpers (Blackwell)
// ---------------------------------------------------------------------------
__device__ __forceinline__ unsigned long long ffma2(unsigned long long a,
                                                    unsigned long long b,
                                                    unsigned long long c) {
    unsigned long long d;
    asm("fma.rn.f32x2 %0, %1, %2, %3;" : "=l"(d) : "l"(a), "l"(b), "l"(c));
    return d;
}
__device__ __forceinline__ float2 u2f(unsigned long long v) {
    float2 f;
    asm("mov.b64 {%0, %1}, %2;" : "=f"(f.x), "=f"(f.y) : "l"(v));
    return f;
}
__device__ __forceinline__ unsigned long long f2u(float lo, float hi) {
    unsigned long long v;
    asm("mov.b64 %0, {%1, %2};" : "=l"(v) : "f"(lo), "f"(hi));
    return v;
}

// ---------------------------------------------------------------------------
// Kernel 1: direction-fused input projection.
// Block t stages x[:, t, :] ONCE. Thread h holds BOTH w_ih_f[h] and w_ih_b[h]
// rows in registers and computes fwd xp[0][t][:,h] and bwd xp[1][T-1-t][:,h]
// in the same pass: each x broadcast LDS fuels 8 MACs/lane instead of 4,
// and the block count halves vs the per-direction version.
// ---------------------------------------------------------------------------
#define IPAD 52
__global__ __launch_bounds__(256) void proj_kernel(
    const float* __restrict__ x,
    const float* __restrict__ w_ih_f, const float* __restrict__ b_ih_f, const float* __restrict__ b_hh_f,
    const float* __restrict__ w_ih_b, const float* __restrict__ b_ih_b, const float* __restrict__ b_hh_b)
{
    __shared__ float xs[B * IPAD];   // 26.6 KB, padded rows

    const int t = blockIdx.x;
    const int h = threadIdx.x;

    // zero padding lanes, then stage x[:, t, :]
    for (int idx = h; idx < B * IPAD; idx += blockDim.x) xs[idx] = 0.f;
    __syncthreads();
    for (int idx = h; idx < B * I; idx += blockDim.x) {
        int b = idx / I;
        int i = idx - b * I;
        xs[b * IPAD + i] = x[((size_t)b * T + t) * I + i];
    }

    // both directions' weight rows in registers (packed pairs, zero-padded)
    unsigned long long wf[26], wb[26];
    {
        const float* pf = w_ih_f + (size_t)h * I;
        const float* pb = w_ih_b + (size_t)h * I;
        #pragma unroll
        for (int i = 0; i < 25; i++) {
            wf[i] = f2u(pf[2 * i], pf[2 * i + 1]);
            wb[i] = f2u(pb[2 * i], pb[2 * i + 1]);
        }
        wf[25] = 0ull;
        wb[25] = 0ull;
    }
    const float biasf = b_ih_f[h] + b_hh_f[h];
    const float biasb = b_ih_b[h] + b_hh_b[h];

    __syncthreads();

    float* xpf = g_xp + (((size_t)0 * T + t) * B) * H + h;             // fwd step t
    float* xpb = g_xp + (((size_t)1 * T + (T - 1 - t)) * B) * H + h;   // bwd step T-1-t
    #pragma unroll 2
    for (int b = 0; b < B; b++) {
        const ulonglong2* xb = reinterpret_cast<const ulonglong2*>(&xs[b * IPAD]);
        unsigned long long f0 = 0ull, f1 = 0ull, g0 = 0ull, g1 = 0ull;
        #pragma unroll
        for (int i = 0; i < 13; i++) {
            ulonglong2 xv = xb[i];
            f0 = ffma2(xv.x, wf[2 * i],     f0);
            f1 = ffma2(xv.y, wf[2 * i + 1], f1);
            g0 = ffma2(xv.x, wb[2 * i],     g0);
            g1 = ffma2(xv.y, wb[2 * i + 1], g1);
        }
        float2 a0 = u2f(f0), a1 = u2f(f1);
        float2 c0 = u2f(g0), c1 = u2f(g1);
        xpf[(size_t)b * H] = biasf + ((a0.x + a0.y) + (a1.x + a1.y));
        xpb[(size_t)b * H] = biasb + ((c0.x + c0.y) + (c1.x + c1.y));
    }
}

// ---------------------------------------------------------------------------
// Kernel 2: recurrence — BYTE-EXACT round-2 version (measured 781 us).
// 128 CTAs: blockIdx/64 = direction, 2 batch rows per CTA.
// Thread t owns neuron n=t. W[t, 0:96] from SMEM (pitch 100), W[t, 96:256] in regs.
// Dot products in packed fp32x2 (FFMA2), 4 independent chains per thread.
// h double-buffered in SMEM, one barrier per step, xp prefetched one step ahead.
// ---------------------------------------------------------------------------
__global__ __launch_bounds__(256, 1) void rnn_kernel(
    const float* __restrict__ w_hh_f,
    const float* __restrict__ w_hh_b,
    float* __restrict__ out)
{
    extern __shared__ float sm[];
    float* Wsh = sm;                       // [256][PITCH]  (102,400 B)
    float* hs  = sm + 256 * PITCH;         // [2 buf][2 rows][256]  (4,096 B)

    const int dir = blockIdx.x >> 6;
    const int j   = blockIdx.x & 63;
    const int b0  = 2 * j;
    const int t   = threadIdx.x;

    const float* __restrict__ W = dir ? w_hh_b : w_hh_f;

    // W[:, 0:K_SMEM] -> smem
    for (int idx = t; idx < 256 * K_SMEM; idx += 256) {
        int n = idx / K_SMEM;
        int k = idx - n * K_SMEM;
        Wsh[n * PITCH + k] = W[n * H + k];
    }
    // W[t, K_SMEM:256] -> regs, as packed (k,k+1) pairs
    ulonglong2 wreg[K_REG / 4];            // 40 x 16B = 160 floats
    {
        const ulonglong2* wrow = reinterpret_cast<const ulonglong2*>(W + (size_t)t * H + K_SMEM);
        #pragma unroll
        for (int r = 0; r < K_REG / 4; r++) wreg[r] = wrow[r];
    }
    hs[0 * 512 + 0 * 256 + t] = 0.f;
    hs[0 * 512 + 1 * 256 + t] = 0.f;
    __syncthreads();

    const float* xp0 = g_xp + ((size_t)dir * T * B + b0) * H + t;
    const float* xp1 = xp0 + H;
    const size_t step_stride = (size_t)B * H;

    float xa = __ldg(xp0);
    float xb = __ldg(xp1);

    float* out_t = out + (size_t)dir * H + t;

    int buf = 0;
    for (int s = 0; s < T; s++) {
        float nxa = 0.f, nxb = 0.f;
        if (s < T - 1) {
            nxa = __ldg(xp0 + (size_t)(s + 1) * step_stride);
            nxb = __ldg(xp1 + (size_t)(s + 1) * step_stride);
        }

        const ulonglong2* h0v = reinterpret_cast<const ulonglong2*>(hs + buf * 512);
        const ulonglong2* h1v = reinterpret_cast<const ulonglong2*>(hs + buf * 512 + 256);
        const ulonglong2* wv  = reinterpret_cast<const ulonglong2*>(Wsh + t * PITCH);

        // 4 independent packed accumulator chains (2 per batch row)
        unsigned long long aA0 = 0ull, aB0 = 0ull, aA1 = 0ull, aB1 = 0ull;

        // k in [0, K_SMEM): W from shared
        #pragma unroll
        for (int i = 0; i < K_SMEM / 4; i++) {
            ulonglong2 w  = wv[i];
            ulonglong2 ha = h0v[i];
            ulonglong2 hb = h1v[i];
            aA0 = ffma2(w.x, ha.x, aA0);
            aB0 = ffma2(w.y, ha.y, aB0);
            aA1 = ffma2(w.x, hb.x, aA1);
            aB1 = ffma2(w.y, hb.y, aB1);
        }
        // k in [K_SMEM, 256): W from regs
        #pragma unroll
        for (int r = 0; r < K_REG / 4; r++) {
            ulonglong2 w  = wreg[r];
            ulonglong2 ha = h0v[K_SMEM / 4 + r];
            ulonglong2 hb = h1v[K_SMEM / 4 + r];
            aA0 = ffma2(w.x, ha.x, aA0);
            aB0 = ffma2(w.y, ha.y, aB0);
            aA1 = ffma2(w.x, hb.x, aA1);
            aB1 = ffma2(w.y, hb.y, aB1);
        }

        float2 fA0 = u2f(aA0), fB0 = u2f(aB0);
        float2 fA1 = u2f(aA1), fB1 = u2f(aB1);
        float h0 = fmaxf(xa + ((fA0.x + fA0.y) + (fB0.x + fB0.y)), 0.f);
        float h1 = fmaxf(xb + ((fA1.x + fA1.y) + (fB1.x + fB1.y)), 0.f);

        const int time = dir ? (T - 1 - s) : s;
        out_t[((size_t)b0 * T + time) * (2 * H)] = h0;
        out_t[((size_t)(b0 + 1) * T + time) * (2 * H)] = h1;

        const int nb = buf ^ 1;
        hs[nb * 512 + t]       = h0;
        hs[nb * 512 + 256 + t] = h1;
        __syncthreads();

        buf = nb;
        xa = nxa;
        xb = nxb;
    }
}

// ---------------------------------------------------------------------------
extern "C" void kernel_launch(void* const* d_in, const int* in_sizes, int n_in,
                              void* d_out, int out_size)
{
    const float* x      = (const float*)d_in[0];
    const float* w_ih_f = (const float*)d_in[1];
    const float* w_hh_f = (const float*)d_in[2];
    const float* b_ih_f = (const float*)d_in[3];
    const float* b_hh_f = (const float*)d_in[4];
    const float* w_ih_b = (const float*)d_in[5];
    const float* w_hh_b = (const float*)d_in[6];
    const float* b_ih_b = (const float*)d_in[7];
    const float* b_hh_b = (const float*)d_in[8];
    float* out = (float*)d_out;

    static bool attr_set = false;
    const int smem_bytes = 256 * PITCH * 4 + 2 * 2 * 256 * 4;  // 102400 + 4096 = 106496
    if (!attr_set) {
        cudaFuncSetAttribute(rnn_kernel, cudaFuncAttributeMaxDynamicSharedMemorySize, smem_bytes);
        attr_set = true;
    }

    // 1) direction-fused input projection (T blocks)
    proj_kernel<<<T, 256>>>(x, w_ih_f, b_ih_f, b_hh_f, w_ih_b, b_ih_b, b_hh_b);

    // 2) recurrence: 128 CTAs (64 per direction, 2 batch rows each)
    rnn_kernel<<<128, 256, smem_bytes>>>(w_hh_f, w_hh_b, out);
}